// round 2
// baseline (speedup 1.0000x reference)
#include <cuda_runtime.h>

#define N_NODES 100000
#define N_EDGES 1250000
#define F 64

// Scratch (device globals — no allocation allowed in kernel_launch)
__device__ float g_deg[N_NODES];
__device__ float g_dinv[N_NODES];
__device__ float g_hs[N_NODES * F];   // h[n][j] * dinv[n]

__global__ void k_init_deg() {
    int i = blockIdx.x * blockDim.x + threadIdx.x;
    if (i < N_NODES) g_deg[i] = 1.0f;   // self-loop contributes 1 to every degree
}

__global__ void k_count(const int* __restrict__ ei) {
    int e = blockIdx.x * blockDim.x + threadIdx.x;
    if (e < N_EDGES) {
        int d = ei[N_EDGES + e];   // dst row
        atomicAdd(&g_deg[d], 1.0f);
    }
}

__global__ void k_dinv() {
    int i = blockIdx.x * blockDim.x + threadIdx.x;
    if (i < N_NODES) g_dinv[i] = rsqrtf(g_deg[i]);  // deg >= 1 always
}

// Fused GEMM + normalization + self-loop + bias:
//   hs[n][j]  = (x[n] . W[j]) * dinv[n]
//   out[n][j] = bias[j] + hs[n][j] * dinv[n]
// Block: 256 threads computes a 64-node x 64-col tile; thread tile 4x4.
__global__ void __launch_bounds__(256) k_gemm(
    const float* __restrict__ x, const float* __restrict__ w,
    const float* __restrict__ bias, float* __restrict__ out)
{
    __shared__ float Xs[64 * 64];
    __shared__ float Ws[64 * 64];
    const int tid = threadIdx.x;
    const int n_base = blockIdx.x * 64;

    // Stage W (row-major [j][k]) — 4096 floats via float4
    {
        const float4* w4 = (const float4*)w;
        float4* ws4 = (float4*)Ws;
        #pragma unroll
        for (int r = 0; r < 4; r++) ws4[tid + 256 * r] = w4[tid + 256 * r];
    }
    // Stage X tile [64 nodes][64 feats], zero-pad past N_NODES
    {
        const float4* x4 = (const float4*)(x + (size_t)n_base * F);
        float4* xs4 = (float4*)Xs;
        int rem_nodes = N_NODES - n_base;
        if (rem_nodes >= 64) {
            #pragma unroll
            for (int r = 0; r < 4; r++) xs4[tid + 256 * r] = x4[tid + 256 * r];
        } else {
            int maxf4 = rem_nodes * 16;
            #pragma unroll
            for (int r = 0; r < 4; r++) {
                int idx = tid + 256 * r;
                xs4[idx] = (idx < maxf4) ? x4[idx] : make_float4(0.f, 0.f, 0.f, 0.f);
            }
        }
    }
    __syncthreads();

    const int tx = tid & 15;    // column group: cols j0..j0+3
    const int ty = tid >> 4;    // node group:   rows n0..n0+3
    const int j0 = tx * 4, n0 = ty * 4;

    float acc[4][4] = {};
    const float4* Xs4 = (const float4*)Xs;
    const float4* Ws4 = (const float4*)Ws;

    #pragma unroll
    for (int k4 = 0; k4 < 16; k4++) {
        float4 xv[4], wv[4];
        #pragma unroll
        for (int i = 0; i < 4; i++) xv[i] = Xs4[(n0 + i) * 16 + k4];
        #pragma unroll
        for (int i = 0; i < 4; i++) wv[i] = Ws4[(j0 + i) * 16 + k4];
        #pragma unroll
        for (int i = 0; i < 4; i++) {
            #pragma unroll
            for (int jj = 0; jj < 4; jj++) {
                acc[i][jj] += xv[i].x * wv[jj].x + xv[i].y * wv[jj].y
                            + xv[i].z * wv[jj].z + xv[i].w * wv[jj].w;
            }
        }
    }

    const float4 b4 = ((const float4*)bias)[tx];
    #pragma unroll
    for (int i = 0; i < 4; i++) {
        int n = n_base + n0 + i;
        if (n < N_NODES) {
            float dv = g_dinv[n];
            float4 hs, o;
            hs.x = acc[i][0] * dv; hs.y = acc[i][1] * dv;
            hs.z = acc[i][2] * dv; hs.w = acc[i][3] * dv;
            o.x = b4.x + hs.x * dv; o.y = b4.y + hs.y * dv;
            o.z = b4.z + hs.z * dv; o.w = b4.w + hs.w * dv;
            ((float4*)g_hs)[n * 16 + tx] = hs;
            ((float4*)out)[n * 16 + tx] = o;
        }
    }
}

// One warp per edge: gather hs[src] (float2 per lane), RED into out[dst].
__global__ void __launch_bounds__(256) k_scatter(
    const int* __restrict__ ei, float* __restrict__ out)
{
    int warp = (int)((blockIdx.x * (unsigned)blockDim.x + threadIdx.x) >> 5);
    int lane = threadIdx.x & 31;
    if (warp >= N_EDGES) return;
    int s = __ldg(&ei[warp]);            // src
    int d = __ldg(&ei[N_EDGES + warp]);  // dst
    float nd = __ldg(&g_dinv[d]);
    float2 v = ((const float2*)g_hs)[s * 32 + lane];
    float* op = out + (size_t)d * F + lane * 2;
    atomicAdd(op,     v.x * nd);   // return unused -> REDG
    atomicAdd(op + 1, v.y * nd);
}

extern "C" void kernel_launch(void* const* d_in, const int* in_sizes, int n_in,
                              void* d_out, int out_size)
{
    const float* x  = (const float*)d_in[0];
    const int*   ei = (const int*)d_in[1];
    const float* w  = (const float*)d_in[2];
    const float* b  = (const float*)d_in[3];
    float*       out = (float*)d_out;
    (void)in_sizes; (void)n_in; (void)out_size;

    k_init_deg<<<(N_NODES + 255) / 256, 256>>>();
    k_count   <<<(N_EDGES + 255) / 256, 256>>>(ei);
    k_dinv    <<<(N_NODES + 255) / 256, 256>>>();
    k_gemm    <<<(N_NODES + 63) / 64, 256>>>(x, w, b, out);

    // one warp per edge
    long long total_threads = (long long)N_EDGES * 32;
    int blocks = (int)((total_threads + 255) / 256);
    k_scatter<<<blocks, 256>>>(ei, out);
}

// round 3
// speedup vs baseline: 2.0831x; 2.0831x over previous
#include <cuda_runtime.h>

#define N_NODES 100000
#define N_EDGES 1250000
#define F 64

// Scratch (device globals — no allocation allowed in kernel_launch)
__device__ float g_deg[N_NODES];
__device__ float g_dinv[N_NODES];
__device__ float g_hs[N_NODES * F];   // h[n][j] * dinv[n]

__global__ void k_init_deg() {
    int i = blockIdx.x * blockDim.x + threadIdx.x;
    if (i < N_NODES) g_deg[i] = 1.0f;   // self-loop contributes 1 to every degree
}

__global__ void k_count(const int* __restrict__ ei) {
    int e = blockIdx.x * blockDim.x + threadIdx.x;
    if (e < N_EDGES) {
        int d = ei[N_EDGES + e];   // dst row
        atomicAdd(&g_deg[d], 1.0f);
    }
}

__global__ void k_dinv() {
    int i = blockIdx.x * blockDim.x + threadIdx.x;
    if (i < N_NODES) g_dinv[i] = rsqrtf(g_deg[i]);  // deg >= 1 always
}

// Fused GEMM + normalization + self-loop + bias:
//   hs[n][j]  = (x[n] . W[j]) * dinv[n]
//   out[n][j] = bias[j] + hs[n][j] * dinv[n]
// Block: 256 threads computes 64 nodes x 64 cols; thread tile 4x4.
// Shared layouts padded to 68 floats (17 float4) per row: conflict-free.
#define XS_STRIDE4 17
#define WT_STRIDE  68
__global__ void __launch_bounds__(256) k_gemm(
    const float* __restrict__ x, const float* __restrict__ w,
    const float* __restrict__ bias, float* __restrict__ out)
{
    __shared__ float Xs[64 * WT_STRIDE];   // [node][k], padded
    __shared__ float Wt[64 * WT_STRIDE];   // [k][j],    padded (transposed W)
    const int tid = threadIdx.x;
    const int n_base = blockIdx.x * 64;

    // Stage W transposed: Wt[k][j] = w[j*64 + k]
    {
        const float4* w4 = (const float4*)w;
        #pragma unroll
        for (int r = 0; r < 4; r++) {
            int idx = tid + 256 * r;        // 0..1023 float4s of W
            float4 v = w4[idx];
            int j  = idx >> 4;              // W row (output col)
            int kq = idx & 15;              // k / 4
            Wt[(4 * kq + 0) * WT_STRIDE + j] = v.x;
            Wt[(4 * kq + 1) * WT_STRIDE + j] = v.y;
            Wt[(4 * kq + 2) * WT_STRIDE + j] = v.z;
            Wt[(4 * kq + 3) * WT_STRIDE + j] = v.w;
        }
    }
    // Stage X tile [64 nodes][64 feats] into padded rows, zero-pad past N_NODES
    {
        const float4* x4 = (const float4*)(x + (size_t)n_base * F);
        float4* xs4 = (float4*)Xs;
        int rem_nodes = N_NODES - n_base;
        int maxf4 = (rem_nodes >= 64) ? 1024 : rem_nodes * 16;
        #pragma unroll
        for (int r = 0; r < 4; r++) {
            int idx = tid + 256 * r;
            float4 v = (idx < maxf4) ? x4[idx] : make_float4(0.f, 0.f, 0.f, 0.f);
            xs4[(idx >> 4) * XS_STRIDE4 + (idx & 15)] = v;
        }
    }
    __syncthreads();

    const int tx = tid & 15;    // column group: cols tx*4 .. tx*4+3
    const int ty = tid >> 4;    // node group:   rows ty*4 .. ty*4+3
    const int n0 = ty * 4;

    float acc[4][4] = {};
    const float4* Xs4 = (const float4*)Xs;
    const float4* Wt4 = (const float4*)Wt;

    #pragma unroll
    for (int k4 = 0; k4 < 16; k4++) {
        float4 xv[4], wv[4];
        #pragma unroll
        for (int i = 0; i < 4; i++) xv[i] = Xs4[(n0 + i) * XS_STRIDE4 + k4];
        #pragma unroll
        for (int kk = 0; kk < 4; kk++) wv[kk] = Wt4[(k4 * 4 + kk) * XS_STRIDE4 + tx];
        #pragma unroll
        for (int i = 0; i < 4; i++) {
            #pragma unroll
            for (int jj = 0; jj < 4; jj++) {
                float wj0 = (jj == 0) ? wv[0].x : (jj == 1) ? wv[0].y : (jj == 2) ? wv[0].z : wv[0].w;
                float wj1 = (jj == 0) ? wv[1].x : (jj == 1) ? wv[1].y : (jj == 2) ? wv[1].z : wv[1].w;
                float wj2 = (jj == 0) ? wv[2].x : (jj == 1) ? wv[2].y : (jj == 2) ? wv[2].z : wv[2].w;
                float wj3 = (jj == 0) ? wv[3].x : (jj == 1) ? wv[3].y : (jj == 2) ? wv[3].z : wv[3].w;
                acc[i][jj] += xv[i].x * wj0 + xv[i].y * wj1
                            + xv[i].z * wj2 + xv[i].w * wj3;
            }
        }
    }

    const float4 b4 = ((const float4*)bias)[tx];
    #pragma unroll
    for (int i = 0; i < 4; i++) {
        int n = n_base + n0 + i;
        if (n < N_NODES) {
            float dv = g_dinv[n];
            float4 hs, o;
            hs.x = acc[i][0] * dv; hs.y = acc[i][1] * dv;
            hs.z = acc[i][2] * dv; hs.w = acc[i][3] * dv;
            o.x = b4.x + hs.x * dv; o.y = b4.y + hs.y * dv;
            o.z = b4.z + hs.z * dv; o.w = b4.w + hs.w * dv;
            ((float4*)g_hs)[n * 16 + tx] = hs;
            ((float4*)out)[n * 16 + tx] = o;
        }
    }
}

// 16 lanes per edge: gather float4 of hs[src], vector-RED into out[dst].
__global__ void __launch_bounds__(256) k_scatter(
    const int* __restrict__ ei, float* __restrict__ out)
{
    long long t = blockIdx.x * (long long)blockDim.x + threadIdx.x;
    int e = (int)(t >> 4);
    int lane16 = threadIdx.x & 15;
    if (e >= N_EDGES) return;
    int s = __ldg(&ei[e]);            // src
    int d = __ldg(&ei[N_EDGES + e]);  // dst
    float nd = __ldg(&g_dinv[d]);
    float4 v = ((const float4*)g_hs)[s * 16 + lane16];
    float* op = out + (size_t)d * F + lane16 * 4;
    asm volatile("red.global.add.v4.f32 [%0], {%1, %2, %3, %4};"
                 :: "l"(op), "f"(v.x * nd), "f"(v.y * nd), "f"(v.z * nd), "f"(v.w * nd)
                 : "memory");
}

extern "C" void kernel_launch(void* const* d_in, const int* in_sizes, int n_in,
                              void* d_out, int out_size)
{
    const float* x  = (const float*)d_in[0];
    const int*   ei = (const int*)d_in[1];
    const float* w  = (const float*)d_in[2];
    const float* b  = (const float*)d_in[3];
    float*       out = (float*)d_out;
    (void)in_sizes; (void)n_in; (void)out_size;

    k_init_deg<<<(N_NODES + 255) / 256, 256>>>();
    k_count   <<<(N_EDGES + 255) / 256, 256>>>(ei);
    k_dinv    <<<(N_NODES + 255) / 256, 256>>>();
    k_gemm    <<<(N_NODES + 63) / 64, 256>>>(x, w, b, out);

    // 16 lanes per edge
    long long total_threads = (long long)N_EDGES * 16;
    int blocks = (int)((total_threads + 255) / 256);
    k_scatter<<<blocks, 256>>>(ei, out);
}

// round 4
// speedup vs baseline: 2.6162x; 1.2559x over previous
#include <cuda_runtime.h>

#define N_NODES 100000
#define N_EDGES 1250000
#define F 64
#define NBLK 391        // ceil(N_NODES/256)

// Scratch (device globals — no allocation allowed in kernel_launch)
__device__ int   g_deg[N_NODES];
__device__ float g_dinv[N_NODES];
__device__ int   g_row_start[N_NODES + 1];
__device__ int   g_cursor[N_NODES];
__device__ int   g_bsum[512];
__device__ int   g_boff[512];
__device__ int   g_ssrc[N_EDGES];       // src ids sorted by dst
__device__ float g_hs[N_NODES * F];     // h[n][j] * dinv[n]

__global__ void k_zero_deg() {
    int i = blockIdx.x * blockDim.x + threadIdx.x;
    if (i < N_NODES) g_deg[i] = 0;
}

__global__ void k_count(const int* __restrict__ ei) {
    int e = blockIdx.x * blockDim.x + threadIdx.x;
    if (e < N_EDGES) atomicAdd(&g_deg[ei[N_EDGES + e]], 1);
}

__global__ void k_dinv() {
    int i = blockIdx.x * blockDim.x + threadIdx.x;
    if (i < N_NODES) g_dinv[i] = rsqrtf((float)g_deg[i] + 1.0f);  // +1 self-loop
}

// ---- exclusive prefix sum over g_deg -> g_row_start ----
__global__ void k_scanA() {   // per-block exclusive scan + block totals
    __shared__ int sd[256];
    int tid = threadIdx.x;
    int i = blockIdx.x * 256 + tid;
    int v = (i < N_NODES) ? g_deg[i] : 0;
    sd[tid] = v;
    __syncthreads();
    #pragma unroll
    for (int off = 1; off < 256; off <<= 1) {
        int t = (tid >= off) ? sd[tid - off] : 0;
        __syncthreads();
        sd[tid] += t;
        __syncthreads();
    }
    if (i < N_NODES) g_row_start[i] = sd[tid] - v;   // exclusive
    if (tid == 255) g_bsum[blockIdx.x] = sd[255];
}

__global__ void k_scanB() {   // single block scans the 391 block totals
    __shared__ int sd[512];
    int tid = threadIdx.x;
    int v = (tid < NBLK) ? g_bsum[tid] : 0;
    sd[tid] = v;
    __syncthreads();
    #pragma unroll
    for (int off = 1; off < 512; off <<= 1) {
        int t = (tid >= off) ? sd[tid - off] : 0;
        __syncthreads();
        sd[tid] += t;
        __syncthreads();
    }
    g_boff[tid] = sd[tid] - v;   // exclusive block offsets
}

__global__ void k_scanC() {   // add offsets, init cursor, cap row_start
    int i = blockIdx.x * 256 + threadIdx.x;
    if (i < N_NODES) {
        int rs = g_row_start[i] + g_boff[blockIdx.x];
        g_row_start[i] = rs;
        g_cursor[i] = rs;
    }
    if (i == 0) g_row_start[N_NODES] = N_EDGES;
}

__global__ void k_place(const int* __restrict__ ei) {
    int e = blockIdx.x * blockDim.x + threadIdx.x;
    if (e < N_EDGES) {
        int d = ei[N_EDGES + e];
        int pos = atomicAdd(&g_cursor[d], 1);
        g_ssrc[pos] = ei[e];
    }
}

// Fused GEMM + source normalization: hs[n][j] = (x[n] . W[j]) * dinv[n]
#define XS_STRIDE4 17
#define WT_STRIDE  68
__global__ void __launch_bounds__(256) k_gemm(
    const float* __restrict__ x, const float* __restrict__ w)
{
    __shared__ float Xs[64 * WT_STRIDE];   // [node][k], padded
    __shared__ float Wt[64 * WT_STRIDE];   // [k][j],    padded (transposed W)
    const int tid = threadIdx.x;
    const int n_base = blockIdx.x * 64;

    {   // Stage W transposed: Wt[k][j] = w[j*64 + k]
        const float4* w4 = (const float4*)w;
        #pragma unroll
        for (int r = 0; r < 4; r++) {
            int idx = tid + 256 * r;
            float4 v = w4[idx];
            int j  = idx >> 4;
            int kq = idx & 15;
            Wt[(4 * kq + 0) * WT_STRIDE + j] = v.x;
            Wt[(4 * kq + 1) * WT_STRIDE + j] = v.y;
            Wt[(4 * kq + 2) * WT_STRIDE + j] = v.z;
            Wt[(4 * kq + 3) * WT_STRIDE + j] = v.w;
        }
    }
    {   // Stage X tile, zero-pad past N_NODES
        const float4* x4 = (const float4*)(x + (size_t)n_base * F);
        float4* xs4 = (float4*)Xs;
        int rem_nodes = N_NODES - n_base;
        int maxf4 = (rem_nodes >= 64) ? 1024 : rem_nodes * 16;
        #pragma unroll
        for (int r = 0; r < 4; r++) {
            int idx = tid + 256 * r;
            float4 v = (idx < maxf4) ? x4[idx] : make_float4(0.f, 0.f, 0.f, 0.f);
            xs4[(idx >> 4) * XS_STRIDE4 + (idx & 15)] = v;
        }
    }
    __syncthreads();

    const int tx = tid & 15;
    const int ty = tid >> 4;
    const int n0 = ty * 4;

    float acc[4][4] = {};
    const float4* Xs4 = (const float4*)Xs;
    const float4* Wt4 = (const float4*)Wt;

    #pragma unroll
    for (int k4 = 0; k4 < 16; k4++) {
        float4 xv[4], wv[4];
        #pragma unroll
        for (int i = 0; i < 4; i++) xv[i] = Xs4[(n0 + i) * XS_STRIDE4 + k4];
        #pragma unroll
        for (int kk = 0; kk < 4; kk++) wv[kk] = Wt4[(k4 * 4 + kk) * XS_STRIDE4 + tx];
        #pragma unroll
        for (int i = 0; i < 4; i++) {
            #pragma unroll
            for (int jj = 0; jj < 4; jj++) {
                float wj0 = (jj == 0) ? wv[0].x : (jj == 1) ? wv[0].y : (jj == 2) ? wv[0].z : wv[0].w;
                float wj1 = (jj == 0) ? wv[1].x : (jj == 1) ? wv[1].y : (jj == 2) ? wv[1].z : wv[1].w;
                float wj2 = (jj == 0) ? wv[2].x : (jj == 1) ? wv[2].y : (jj == 2) ? wv[2].z : wv[2].w;
                float wj3 = (jj == 0) ? wv[3].x : (jj == 1) ? wv[3].y : (jj == 2) ? wv[3].z : wv[3].w;
                acc[i][jj] += xv[i].x * wj0 + xv[i].y * wj1
                            + xv[i].z * wj2 + xv[i].w * wj3;
            }
        }
    }

    #pragma unroll
    for (int i = 0; i < 4; i++) {
        int n = n_base + n0 + i;
        if (n < N_NODES) {
            float dv = g_dinv[n];
            float4 hs;
            hs.x = acc[i][0] * dv; hs.y = acc[i][1] * dv;
            hs.z = acc[i][2] * dv; hs.w = acc[i][3] * dv;
            ((float4*)g_hs)[n * 16 + tx] = hs;
        }
    }
}

// CSR gather: 16 lanes per node; register accumulation; single store.
// out[d] = bias + dinv[d] * (hs[d] + sum_{e in row d} hs[src_e])
__global__ void __launch_bounds__(256) k_gather(
    const float* __restrict__ bias, float* __restrict__ out)
{
    long long t = blockIdx.x * (long long)blockDim.x + threadIdx.x;
    int node = (int)(t >> 4);
    int lane = threadIdx.x & 15;
    if (node >= N_NODES) return;

    const float4* hs4 = (const float4*)g_hs;
    float4 acc = hs4[node * 16 + lane];   // self-loop term
    int e   = __ldg(&g_row_start[node]);
    int end = __ldg(&g_row_start[node + 1]);

    for (; e + 2 <= end; e += 2) {
        int s0 = __ldg(&g_ssrc[e]);
        int s1 = __ldg(&g_ssrc[e + 1]);
        float4 v0 = hs4[s0 * 16 + lane];
        float4 v1 = hs4[s1 * 16 + lane];
        acc.x += v0.x + v1.x; acc.y += v0.y + v1.y;
        acc.z += v0.z + v1.z; acc.w += v0.w + v1.w;
    }
    if (e < end) {
        int s0 = __ldg(&g_ssrc[e]);
        float4 v0 = hs4[s0 * 16 + lane];
        acc.x += v0.x; acc.y += v0.y; acc.z += v0.z; acc.w += v0.w;
    }

    float dv = __ldg(&g_dinv[node]);
    float4 b4 = ((const float4*)bias)[lane];
    float4 o;
    o.x = b4.x + dv * acc.x; o.y = b4.y + dv * acc.y;
    o.z = b4.z + dv * acc.z; o.w = b4.w + dv * acc.w;
    ((float4*)out)[node * 16 + lane] = o;
}

extern "C" void kernel_launch(void* const* d_in, const int* in_sizes, int n_in,
                              void* d_out, int out_size)
{
    const float* x  = (const float*)d_in[0];
    const int*   ei = (const int*)d_in[1];
    const float* w  = (const float*)d_in[2];
    const float* b  = (const float*)d_in[3];
    float*       out = (float*)d_out;
    (void)in_sizes; (void)n_in; (void)out_size;

    k_zero_deg<<<NBLK, 256>>>();
    k_count   <<<(N_EDGES + 255) / 256, 256>>>(ei);
    k_dinv    <<<NBLK, 256>>>();
    k_scanA   <<<NBLK, 256>>>();
    k_scanB   <<<1, 512>>>();
    k_scanC   <<<NBLK, 256>>>();
    k_place   <<<(N_EDGES + 255) / 256, 256>>>(ei);
    k_gemm    <<<(N_NODES + 63) / 64, 256>>>(x, w);

    long long total_threads = (long long)N_NODES * 16;
    int blocks = (int)((total_threads + 255) / 256);
    k_gather<<<blocks, 256>>>(b, out);
}

// round 5
// speedup vs baseline: 2.8594x; 1.0930x over previous
#include <cuda_runtime.h>
#include <cuda_fp16.h>

#define N_NODES 100000
#define N_EDGES 1250000
#define F 64
#define NBLK 391        // ceil(N_NODES/256)

// Scratch (device globals — no allocation allowed in kernel_launch)
__device__ int   g_deg[N_NODES];
__device__ float g_dinv[N_NODES];
__device__ int   g_row_start[N_NODES + 1];
__device__ int   g_cursor[N_NODES];
__device__ int   g_bsum[512];
__device__ int   g_boff[512];
__device__ int   g_ssrc[N_EDGES];        // src ids sorted by dst
__device__ uint2 g_hs[N_NODES * 16];     // fp16 hs: 64 halves/row = 16 uint2

__global__ void k_zero_deg() {
    int i = blockIdx.x * blockDim.x + threadIdx.x;
    if (i < N_NODES) g_deg[i] = 0;
}

__global__ void k_count(const int* __restrict__ ei) {
    int e = blockIdx.x * blockDim.x + threadIdx.x;
    if (e < N_EDGES) atomicAdd(&g_deg[ei[N_EDGES + e]], 1);
}

// per-block exclusive scan + block totals; also computes dinv (fused)
__global__ void k_scanA() {
    __shared__ int sd[256];
    int tid = threadIdx.x;
    int i = blockIdx.x * 256 + tid;
    int v = (i < N_NODES) ? g_deg[i] : 0;
    sd[tid] = v;
    __syncthreads();
    #pragma unroll
    for (int off = 1; off < 256; off <<= 1) {
        int t = (tid >= off) ? sd[tid - off] : 0;
        __syncthreads();
        sd[tid] += t;
        __syncthreads();
    }
    if (i < N_NODES) {
        g_row_start[i] = sd[tid] - v;                 // exclusive
        g_dinv[i] = rsqrtf((float)v + 1.0f);          // +1 self-loop
    }
    if (tid == 255) g_bsum[blockIdx.x] = sd[255];
}

__global__ void k_scanB() {   // single block scans the 391 block totals
    __shared__ int sd[512];
    int tid = threadIdx.x;
    int v = (tid < NBLK) ? g_bsum[tid] : 0;
    sd[tid] = v;
    __syncthreads();
    #pragma unroll
    for (int off = 1; off < 512; off <<= 1) {
        int t = (tid >= off) ? sd[tid - off] : 0;
        __syncthreads();
        sd[tid] += t;
        __syncthreads();
    }
    g_boff[tid] = sd[tid] - v;   // exclusive block offsets
}

__global__ void k_scanC() {   // add offsets, init cursor, cap row_start
    int i = blockIdx.x * 256 + threadIdx.x;
    if (i < N_NODES) {
        int rs = g_row_start[i] + g_boff[blockIdx.x];
        g_row_start[i] = rs;
        g_cursor[i] = rs;
    }
    if (i == 0) g_row_start[N_NODES] = N_EDGES;
}

__global__ void k_place(const int* __restrict__ ei) {
    int e = blockIdx.x * blockDim.x + threadIdx.x;
    if (e < N_EDGES) {
        int d = ei[N_EDGES + e];
        int pos = atomicAdd(&g_cursor[d], 1);
        g_ssrc[pos] = ei[e];
    }
}

// Fused GEMM + source normalization: hs[n][j] = (x[n] . W[j]) * dinv[n], fp16
#define XS_STRIDE4 17
#define WT_STRIDE  68
__global__ void __launch_bounds__(256) k_gemm(
    const float* __restrict__ x, const float* __restrict__ w)
{
    __shared__ float Xs[64 * WT_STRIDE];   // [node][k], padded
    __shared__ float Wt[64 * WT_STRIDE];   // [k][j],    padded (transposed W)
    const int tid = threadIdx.x;
    const int n_base = blockIdx.x * 64;

    {   // Stage W transposed: Wt[k][j] = w[j*64 + k]
        const float4* w4 = (const float4*)w;
        #pragma unroll
        for (int r = 0; r < 4; r++) {
            int idx = tid + 256 * r;
            float4 v = w4[idx];
            int j  = idx >> 4;
            int kq = idx & 15;
            Wt[(4 * kq + 0) * WT_STRIDE + j] = v.x;
            Wt[(4 * kq + 1) * WT_STRIDE + j] = v.y;
            Wt[(4 * kq + 2) * WT_STRIDE + j] = v.z;
            Wt[(4 * kq + 3) * WT_STRIDE + j] = v.w;
        }
    }
    {   // Stage X tile, zero-pad past N_NODES
        const float4* x4 = (const float4*)(x + (size_t)n_base * F);
        float4* xs4 = (float4*)Xs;
        int rem_nodes = N_NODES - n_base;
        int maxf4 = (rem_nodes >= 64) ? 1024 : rem_nodes * 16;
        #pragma unroll
        for (int r = 0; r < 4; r++) {
            int idx = tid + 256 * r;
            float4 v = (idx < maxf4) ? x4[idx] : make_float4(0.f, 0.f, 0.f, 0.f);
            xs4[(idx >> 4) * XS_STRIDE4 + (idx & 15)] = v;
        }
    }
    __syncthreads();

    const int tx = tid & 15;
    const int ty = tid >> 4;
    const int n0 = ty * 4;

    float acc[4][4] = {};
    const float4* Xs4 = (const float4*)Xs;
    const float4* Wt4 = (const float4*)Wt;

    #pragma unroll
    for (int k4 = 0; k4 < 16; k4++) {
        float4 xv[4], wv[4];
        #pragma unroll
        for (int i = 0; i < 4; i++) xv[i] = Xs4[(n0 + i) * XS_STRIDE4 + k4];
        #pragma unroll
        for (int kk = 0; kk < 4; kk++) wv[kk] = Wt4[(k4 * 4 + kk) * XS_STRIDE4 + tx];
        #pragma unroll
        for (int i = 0; i < 4; i++) {
            #pragma unroll
            for (int jj = 0; jj < 4; jj++) {
                float wj0 = (jj == 0) ? wv[0].x : (jj == 1) ? wv[0].y : (jj == 2) ? wv[0].z : wv[0].w;
                float wj1 = (jj == 0) ? wv[1].x : (jj == 1) ? wv[1].y : (jj == 2) ? wv[1].z : wv[1].w;
                float wj2 = (jj == 0) ? wv[2].x : (jj == 1) ? wv[2].y : (jj == 2) ? wv[2].z : wv[2].w;
                float wj3 = (jj == 0) ? wv[3].x : (jj == 1) ? wv[3].y : (jj == 2) ? wv[3].z : wv[3].w;
                acc[i][jj] += xv[i].x * wj0 + xv[i].y * wj1
                            + xv[i].z * wj2 + xv[i].w * wj3;
            }
        }
    }

    #pragma unroll
    for (int i = 0; i < 4; i++) {
        int n = n_base + n0 + i;
        if (n < N_NODES) {
            float dv = g_dinv[n];
            __half2 p0 = __floats2half2_rn(acc[i][0] * dv, acc[i][1] * dv);
            __half2 p1 = __floats2half2_rn(acc[i][2] * dv, acc[i][3] * dv);
            uint2 u;
            u.x = *reinterpret_cast<unsigned*>(&p0);
            u.y = *reinterpret_cast<unsigned*>(&p1);
            g_hs[n * 16 + tx] = u;
        }
    }
}

__device__ __forceinline__ void acc8(float* a, uint4 v) {
    const __half2* h = reinterpret_cast<const __half2*>(&v);
    #pragma unroll
    for (int q = 0; q < 4; q++) {
        float2 f = __half22float2(h[q]);
        a[2 * q]     += f.x;
        a[2 * q + 1] += f.y;
    }
}

// CSR gather: 8 lanes per node; one LDG.128 (8 halves) per edge per lane.
// out[d] = bias + dinv[d] * (hs[d] + sum_{e in row d} hs[src_e])
__global__ void __launch_bounds__(256) k_gather(
    const float* __restrict__ bias, float* __restrict__ out)
{
    long long t = blockIdx.x * (long long)blockDim.x + threadIdx.x;
    int node = (int)(t >> 3);
    int lane = threadIdx.x & 7;
    if (node >= N_NODES) return;

    const uint4* hs16 = (const uint4*)g_hs;   // 8 uint4 per row
    float a[8] = {0.f, 0.f, 0.f, 0.f, 0.f, 0.f, 0.f, 0.f};
    acc8(a, hs16[node * 8 + lane]);           // self-loop term

    int e   = __ldg(&g_row_start[node]);
    int end = __ldg(&g_row_start[node + 1]);

    for (; e + 2 <= end; e += 2) {
        int s0 = __ldg(&g_ssrc[e]);
        int s1 = __ldg(&g_ssrc[e + 1]);
        uint4 v0 = hs16[s0 * 8 + lane];
        uint4 v1 = hs16[s1 * 8 + lane];
        acc8(a, v0);
        acc8(a, v1);
    }
    if (e < end) {
        int s0 = __ldg(&g_ssrc[e]);
        acc8(a, hs16[s0 * 8 + lane]);
    }

    float dv = __ldg(&g_dinv[node]);
    const float4* b4 = (const float4*)bias;
    float4 ba = b4[lane * 2], bb = b4[lane * 2 + 1];
    float4 o0, o1;
    o0.x = ba.x + dv * a[0]; o0.y = ba.y + dv * a[1];
    o0.z = ba.z + dv * a[2]; o0.w = ba.w + dv * a[3];
    o1.x = bb.x + dv * a[4]; o1.y = bb.y + dv * a[5];
    o1.z = bb.z + dv * a[6]; o1.w = bb.w + dv * a[7];
    ((float4*)out)[node * 16 + lane * 2]     = o0;
    ((float4*)out)[node * 16 + lane * 2 + 1] = o1;
}

extern "C" void kernel_launch(void* const* d_in, const int* in_sizes, int n_in,
                              void* d_out, int out_size)
{
    const float* x  = (const float*)d_in[0];
    const int*   ei = (const int*)d_in[1];
    const float* w  = (const float*)d_in[2];
    const float* b  = (const float*)d_in[3];
    float*       out = (float*)d_out;
    (void)in_sizes; (void)n_in; (void)out_size;

    k_zero_deg<<<NBLK, 256>>>();
    k_count   <<<(N_EDGES + 255) / 256, 256>>>(ei);
    k_scanA   <<<NBLK, 256>>>();
    k_scanB   <<<1, 512>>>();
    k_scanC   <<<NBLK, 256>>>();
    k_place   <<<(N_EDGES + 255) / 256, 256>>>(ei);
    k_gemm    <<<(N_NODES + 63) / 64, 256>>>(x, w);

    long long total_threads = (long long)N_NODES * 8;
    int blocks = (int)((total_threads + 255) / 256);
    k_gather<<<blocks, 256>>>(b, out);
}

// round 6
// speedup vs baseline: 3.4152x; 1.1944x over previous
#include <cuda_runtime.h>
#include <cuda_fp16.h>

#define N_NODES 100000
#define N_EDGES 1250000
#define F 64
#define NBLK 391        // ceil(N_NODES/256)

// Scratch (device globals — no allocation allowed in kernel_launch)
__device__ int   g_deg[N_NODES];
__device__ float g_dinv[N_NODES];
__device__ int   g_row_start[N_NODES + 1];
__device__ int   g_cursor[N_NODES];
__device__ int   g_bsum[512];
__device__ int   g_ssrc[N_EDGES];                    // src ids sorted by dst
__device__ __align__(16) __half g_hs[N_NODES * F];   // fp16 hs

__global__ void k_zero_deg() {
    int i = blockIdx.x * blockDim.x + threadIdx.x;
    if (i < N_NODES) g_deg[i] = 0;
}

__global__ void k_count(const int* __restrict__ ei) {
    int e = blockIdx.x * blockDim.x + threadIdx.x;
    if (e < N_EDGES) atomicAdd(&g_deg[ei[N_EDGES + e]], 1);
}

// per-block exclusive scan + block totals; also computes dinv (fused)
__global__ void k_scanA() {
    __shared__ int sd[256];
    int tid = threadIdx.x;
    int i = blockIdx.x * 256 + tid;
    int v = (i < N_NODES) ? g_deg[i] : 0;
    sd[tid] = v;
    __syncthreads();
    #pragma unroll
    for (int off = 1; off < 256; off <<= 1) {
        int t = (tid >= off) ? sd[tid - off] : 0;
        __syncthreads();
        sd[tid] += t;
        __syncthreads();
    }
    if (i < N_NODES) {
        g_row_start[i] = sd[tid] - v;                 // exclusive (within block)
        g_dinv[i] = rsqrtf((float)v + 1.0f);          // +1 self-loop
    }
    if (tid == 255) g_bsum[blockIdx.x] = sd[255];
}

// fused: reduce previous block-sums + add offsets + init cursor
__global__ void k_scanC() {
    __shared__ int sd[256];
    int tid = threadIdx.x;
    int s = 0;
    for (int i = tid; i < blockIdx.x; i += 256) s += g_bsum[i];
    sd[tid] = s;
    __syncthreads();
    #pragma unroll
    for (int off = 128; off > 0; off >>= 1) {
        if (tid < off) sd[tid] += sd[tid + off];
        __syncthreads();
    }
    int boff = sd[0];
    int i = blockIdx.x * 256 + tid;
    if (i < N_NODES) {
        int rs = g_row_start[i] + boff;
        g_row_start[i] = rs;
        g_cursor[i] = rs;
    }
    if (i == 0) g_row_start[N_NODES] = N_EDGES;
}

__global__ void k_place(const int* __restrict__ ei) {
    int e = blockIdx.x * blockDim.x + threadIdx.x;
    if (e < N_EDGES) {
        int d = ei[N_EDGES + e];
        int pos = atomicAdd(&g_cursor[d], 1);
        g_ssrc[pos] = ei[e];
    }
}

// ---- tensor-core GEMM: hs[n][j] = (x[n] . W[j]) * dinv[n], fp16 out ----
__device__ __forceinline__ unsigned pack_h2(float lo, float hi) {
    __half2 h = __floats2half2_rn(lo, hi);   // lo -> low half
    return *reinterpret_cast<unsigned*>(&h);
}

__device__ __forceinline__ void mma16816(float* c,
    unsigned a0, unsigned a1, unsigned a2, unsigned a3,
    unsigned b0, unsigned b1)
{
    asm volatile(
        "mma.sync.aligned.m16n8k16.row.col.f32.f16.f16.f32 "
        "{%0,%1,%2,%3}, {%4,%5,%6,%7}, {%8,%9}, {%0,%1,%2,%3};"
        : "+f"(c[0]), "+f"(c[1]), "+f"(c[2]), "+f"(c[3])
        : "r"(a0), "r"(a1), "r"(a2), "r"(a3), "r"(b0), "r"(b1));
}

#define WH_STRIDE 72   // halves per row (64 + 8 pad) -> conflict-free LDS.32
__global__ void __launch_bounds__(128) k_gemm(
    const float* __restrict__ x, const float* __restrict__ w)
{
    __shared__ __half Wh[64 * WH_STRIDE];   // [j][k] halves
    const int tid = threadIdx.x;

    // Stage W as fp16: 2048 float2 by 128 threads
    {
        const float2* w2 = (const float2*)w;
        #pragma unroll
        for (int r = 0; r < 16; r++) {
            int idx = tid + 128 * r;       // float2 index 0..2047
            int j  = idx >> 5;             // 32 float2 per W row
            int kp = idx & 31;
            float2 v = w2[idx];
            *reinterpret_cast<unsigned*>(&Wh[j * WH_STRIDE + kp * 2]) = pack_h2(v.x, v.y);
        }
    }
    __syncthreads();

    const int warp = tid >> 5, lane = tid & 31;
    const int g = lane >> 2, t = lane & 3;
    const int r0 = blockIdx.x * 64 + warp * 16 + g;   // A rows r0, r0+8
    const int r1 = r0 + 8;
    const bool v0 = r0 < N_NODES, v1 = r1 < N_NODES;
    const float* xr0 = x + (size_t)r0 * F;
    const float* xr1 = x + (size_t)r1 * F;

    float acc[8][4] = {};   // 8 n-tiles x (c0..c3)

    #pragma unroll
    for (int kc = 0; kc < 4; kc++) {
        const int k0 = kc * 16 + t * 2;
        float2 f;
        f = v0 ? *(const float2*)(xr0 + k0)     : make_float2(0.f, 0.f);
        unsigned a0 = pack_h2(f.x, f.y);
        f = v1 ? *(const float2*)(xr1 + k0)     : make_float2(0.f, 0.f);
        unsigned a1 = pack_h2(f.x, f.y);
        f = v0 ? *(const float2*)(xr0 + k0 + 8) : make_float2(0.f, 0.f);
        unsigned a2 = pack_h2(f.x, f.y);
        f = v1 ? *(const float2*)(xr1 + k0 + 8) : make_float2(0.f, 0.f);
        unsigned a3 = pack_h2(f.x, f.y);

        const int kk = kc * 16 + t * 2;   // B k index
        #pragma unroll
        for (int nt = 0; nt < 8; nt++) {
            int n = nt * 8 + g;           // B col (output feature j)
            unsigned b0 = *reinterpret_cast<const unsigned*>(&Wh[n * WH_STRIDE + kk]);
            unsigned b1 = *reinterpret_cast<const unsigned*>(&Wh[n * WH_STRIDE + kk + 8]);
            mma16816(acc[nt], a0, a1, a2, a3, b0, b1);
        }
    }

    // Epilogue: scale by dinv, store fp16
    float dv0 = v0 ? g_dinv[r0] : 0.f;
    float dv1 = v1 ? g_dinv[r1] : 0.f;
    #pragma unroll
    for (int nt = 0; nt < 8; nt++) {
        int col = nt * 8 + t * 2;         // D cols col, col+1
        if (v0)
            *reinterpret_cast<unsigned*>(&g_hs[r0 * F + col]) =
                pack_h2(acc[nt][0] * dv0, acc[nt][1] * dv0);
        if (v1)
            *reinterpret_cast<unsigned*>(&g_hs[r1 * F + col]) =
                pack_h2(acc[nt][2] * dv1, acc[nt][3] * dv1);
    }
}

__device__ __forceinline__ void acc8(float* a, uint4 v) {
    const __half2* h = reinterpret_cast<const __half2*>(&v);
    #pragma unroll
    for (int q = 0; q < 4; q++) {
        float2 f = __half22float2(h[q]);
        a[2 * q]     += f.x;
        a[2 * q + 1] += f.y;
    }
}

// CSR gather: 8 lanes per node; one LDG.128 (8 halves) per edge per lane.
__global__ void __launch_bounds__(256) k_gather(
    const float* __restrict__ bias, float* __restrict__ out)
{
    long long tt = blockIdx.x * (long long)blockDim.x + threadIdx.x;
    int node = (int)(tt >> 3);
    int lane = threadIdx.x & 7;
    if (node >= N_NODES) return;

    const uint4* hs16 = (const uint4*)g_hs;   // 8 uint4 per row
    float a[8] = {0.f, 0.f, 0.f, 0.f, 0.f, 0.f, 0.f, 0.f};
    acc8(a, hs16[node * 8 + lane]);           // self-loop term

    int e   = __ldg(&g_row_start[node]);
    int end = __ldg(&g_row_start[node + 1]);

    for (; e + 2 <= end; e += 2) {
        int s0 = __ldg(&g_ssrc[e]);
        int s1 = __ldg(&g_ssrc[e + 1]);
        uint4 u0 = hs16[s0 * 8 + lane];
        uint4 u1 = hs16[s1 * 8 + lane];
        acc8(a, u0);
        acc8(a, u1);
    }
    if (e < end) {
        int s0 = __ldg(&g_ssrc[e]);
        acc8(a, hs16[s0 * 8 + lane]);
    }

    float dv = __ldg(&g_dinv[node]);
    const float4* b4 = (const float4*)bias;
    float4 ba = b4[lane * 2], bb = b4[lane * 2 + 1];
    float4 o0, o1;
    o0.x = ba.x + dv * a[0]; o0.y = ba.y + dv * a[1];
    o0.z = ba.z + dv * a[2]; o0.w = ba.w + dv * a[3];
    o1.x = bb.x + dv * a[4]; o1.y = bb.y + dv * a[5];
    o1.z = bb.z + dv * a[6]; o1.w = bb.w + dv * a[7];
    ((float4*)out)[node * 16 + lane * 2]     = o0;
    ((float4*)out)[node * 16 + lane * 2 + 1] = o1;
}

extern "C" void kernel_launch(void* const* d_in, const int* in_sizes, int n_in,
                              void* d_out, int out_size)
{
    const float* x  = (const float*)d_in[0];
    const int*   ei = (const int*)d_in[1];
    const float* w  = (const float*)d_in[2];
    const float* b  = (const float*)d_in[3];
    float*       out = (float*)d_out;
    (void)in_sizes; (void)n_in; (void)out_size;

    k_zero_deg<<<NBLK, 256>>>();
    k_count   <<<(N_EDGES + 255) / 256, 256>>>(ei);
    k_scanA   <<<NBLK, 256>>>();
    k_scanC   <<<NBLK, 256>>>();
    k_place   <<<(N_EDGES + 255) / 256, 256>>>(ei);
    k_gemm    <<<(N_NODES + 63) / 64, 128>>>(x, w);

    long long total_threads = (long long)N_NODES * 8;
    int blocks = (int)((total_threads + 255) / 256);
    k_gather<<<blocks, 256>>>(b, out);
}

// round 7
// speedup vs baseline: 3.6143x; 1.0583x over previous
#include <cuda_runtime.h>
#include <cuda_fp16.h>

#define N_NODES 100000
#define N_EDGES 1250000
#define F 64
#define NBLK 391        // ceil(N_NODES/256)

// Scratch (device globals — no allocation allowed in kernel_launch)
__device__ int   g_deg[N_NODES];
__device__ float g_dinv[N_NODES];
__device__ int   g_row_start[N_NODES + 1];
__device__ int   g_cursor[N_NODES];
__device__ unsigned long long g_bsv[512];            // flagged block sums
__device__ int   g_ssrc[N_EDGES];                    // src ids sorted by dst
__device__ __align__(16) __half g_hs[N_NODES * F];   // fp16 hs

__global__ void k_zero() {
    int i = blockIdx.x * blockDim.x + threadIdx.x;
    if (i < N_NODES) g_deg[i] = 0;
    if (i < 512) g_bsv[i] = 0ULL;
}

__global__ void k_count(const int* __restrict__ ei) {
    int e = blockIdx.x * blockDim.x + threadIdx.x;
    if (e < N_EDGES) atomicAdd(&g_deg[ei[N_EDGES + e]], 1);
}

// Single-pass exclusive scan over g_deg (publish block total, poll predecessors)
// + dinv + cursor init, all fused.
__global__ void k_scanF() {
    __shared__ int sd[256];
    const int tid = threadIdx.x, bid = blockIdx.x;
    const int i = bid * 256 + tid;
    int v = (i < N_NODES) ? g_deg[i] : 0;
    sd[tid] = v;
    __syncthreads();
    #pragma unroll
    for (int off = 1; off < 256; off <<= 1) {
        int t = (tid >= off) ? sd[tid - off] : 0;
        __syncthreads();
        sd[tid] += t;
        __syncthreads();
    }
    int incl = sd[tid];
    // publish own block total BEFORE polling predecessors (no circular wait)
    if (tid == 255)
        atomicExch(&g_bsv[bid], (1ULL << 63) | (unsigned long long)(unsigned)incl);

    // poll predecessors: thread t handles p = t, t+256 (< bid)
    int s = 0;
    for (int p = tid; p < bid; p += 256) {
        unsigned long long x;
        do { x = atomicAdd(&g_bsv[p], 0ULL); } while (!(x >> 63));
        s += (int)(unsigned)x;
    }
    __syncthreads();
    sd[tid] = s;
    __syncthreads();
    #pragma unroll
    for (int off = 128; off > 0; off >>= 1) {
        if (tid < off) sd[tid] += sd[tid + off];
        __syncthreads();
    }
    int boff = sd[0];

    if (i < N_NODES) {
        int rs = incl - v + boff;            // exclusive global offset
        g_row_start[i] = rs;
        g_cursor[i] = rs;
        g_dinv[i] = rsqrtf((float)v + 1.0f); // +1 self-loop
    }
    if (i == 0) g_row_start[N_NODES] = N_EDGES;
}

__global__ void k_place(const int* __restrict__ ei) {
    int e = blockIdx.x * blockDim.x + threadIdx.x;
    if (e < N_EDGES) {
        int d = ei[N_EDGES + e];
        int pos = atomicAdd(&g_cursor[d], 1);
        g_ssrc[pos] = ei[e];
    }
}

// ---- tensor-core GEMM: hs[n][j] = (x[n] . W[j]) * dinv[n], fp16 out ----
__device__ __forceinline__ unsigned pack_h2(float lo, float hi) {
    __half2 h = __floats2half2_rn(lo, hi);   // lo -> low half
    return *reinterpret_cast<unsigned*>(&h);
}

__device__ __forceinline__ void mma16816(float* c,
    unsigned a0, unsigned a1, unsigned a2, unsigned a3,
    unsigned b0, unsigned b1)
{
    asm volatile(
        "mma.sync.aligned.m16n8k16.row.col.f32.f16.f16.f32 "
        "{%0,%1,%2,%3}, {%4,%5,%6,%7}, {%8,%9}, {%0,%1,%2,%3};"
        : "+f"(c[0]), "+f"(c[1]), "+f"(c[2]), "+f"(c[3])
        : "r"(a0), "r"(a1), "r"(a2), "r"(a3), "r"(b0), "r"(b1));
}

#define WH_STRIDE 72   // halves per row (64 + 8 pad) -> conflict-free LDS.32
__global__ void __launch_bounds__(128) k_gemm(
    const float* __restrict__ x, const float* __restrict__ w)
{
    __shared__ __half Wh[64 * WH_STRIDE];   // [j][k] halves
    const int tid = threadIdx.x;

    {   // Stage W as fp16: 2048 float2 by 128 threads
        const float2* w2 = (const float2*)w;
        #pragma unroll
        for (int r = 0; r < 16; r++) {
            int idx = tid + 128 * r;       // float2 index 0..2047
            int j  = idx >> 5;             // 32 float2 per W row
            int kp = idx & 31;
            float2 v = w2[idx];
            *reinterpret_cast<unsigned*>(&Wh[j * WH_STRIDE + kp * 2]) = pack_h2(v.x, v.y);
        }
    }
    __syncthreads();

    const int warp = tid >> 5, lane = tid & 31;
    const int g = lane >> 2, t = lane & 3;
    const int r0 = blockIdx.x * 64 + warp * 16 + g;   // A rows r0, r0+8
    const int r1 = r0 + 8;
    const bool v0 = r0 < N_NODES, v1 = r1 < N_NODES;
    const float* xr0 = x + (size_t)r0 * F;
    const float* xr1 = x + (size_t)r1 * F;

    float acc[8][4] = {};   // 8 n-tiles x (c0..c3)

    #pragma unroll
    for (int kc = 0; kc < 4; kc++) {
        const int k0 = kc * 16 + t * 2;
        float2 f;
        f = v0 ? *(const float2*)(xr0 + k0)     : make_float2(0.f, 0.f);
        unsigned a0 = pack_h2(f.x, f.y);
        f = v1 ? *(const float2*)(xr1 + k0)     : make_float2(0.f, 0.f);
        unsigned a1 = pack_h2(f.x, f.y);
        f = v0 ? *(const float2*)(xr0 + k0 + 8) : make_float2(0.f, 0.f);
        unsigned a2 = pack_h2(f.x, f.y);
        f = v1 ? *(const float2*)(xr1 + k0 + 8) : make_float2(0.f, 0.f);
        unsigned a3 = pack_h2(f.x, f.y);

        const int kk = kc * 16 + t * 2;   // B k index
        #pragma unroll
        for (int nt = 0; nt < 8; nt++) {
            int n = nt * 8 + g;           // B col (output feature j)
            unsigned b0 = *reinterpret_cast<const unsigned*>(&Wh[n * WH_STRIDE + kk]);
            unsigned b1 = *reinterpret_cast<const unsigned*>(&Wh[n * WH_STRIDE + kk + 8]);
            mma16816(acc[nt], a0, a1, a2, a3, b0, b1);
        }
    }

    // Epilogue: scale by dinv, store fp16
    float dv0 = v0 ? g_dinv[r0] : 0.f;
    float dv1 = v1 ? g_dinv[r1] : 0.f;
    #pragma unroll
    for (int nt = 0; nt < 8; nt++) {
        int col = nt * 8 + t * 2;         // D cols col, col+1
        if (v0)
            *reinterpret_cast<unsigned*>(&g_hs[r0 * F + col]) =
                pack_h2(acc[nt][0] * dv0, acc[nt][1] * dv0);
        if (v1)
            *reinterpret_cast<unsigned*>(&g_hs[r1 * F + col]) =
                pack_h2(acc[nt][2] * dv1, acc[nt][3] * dv1);
    }
}

__device__ __forceinline__ void acc8(float* a, uint4 v) {
    const __half2* h = reinterpret_cast<const __half2*>(&v);
    #pragma unroll
    for (int q = 0; q < 4; q++) {
        float2 f = __half22float2(h[q]);
        a[2 * q]     += f.x;
        a[2 * q + 1] += f.y;
    }
}

// CSR gather: 8 lanes per node; one LDG.128 (8 halves) per edge per lane.
__global__ void __launch_bounds__(256) k_gather(
    const float* __restrict__ bias, float* __restrict__ out)
{
    long long tt = blockIdx.x * (long long)blockDim.x + threadIdx.x;
    int node = (int)(tt >> 3);
    int lane = threadIdx.x & 7;
    if (node >= N_NODES) return;

    const uint4* hs16 = (const uint4*)g_hs;   // 8 uint4 per row
    float a[8] = {0.f, 0.f, 0.f, 0.f, 0.f, 0.f, 0.f, 0.f};
    acc8(a, hs16[node * 8 + lane]);           // self-loop term

    int e   = __ldg(&g_row_start[node]);
    int end = __ldg(&g_row_start[node + 1]);

    for (; e + 2 <= end; e += 2) {
        int s0 = __ldg(&g_ssrc[e]);
        int s1 = __ldg(&g_ssrc[e + 1]);
        uint4 u0 = hs16[s0 * 8 + lane];
        uint4 u1 = hs16[s1 * 8 + lane];
        acc8(a, u0);
        acc8(a, u1);
    }
    if (e < end) {
        int s0 = __ldg(&g_ssrc[e]);
        acc8(a, hs16[s0 * 8 + lane]);
    }

    float dv = __ldg(&g_dinv[node]);
    const float4* b4 = (const float4*)bias;
    float4 ba = b4[lane * 2], bb = b4[lane * 2 + 1];
    float4 o0, o1;
    o0.x = ba.x + dv * a[0]; o0.y = ba.y + dv * a[1];
    o0.z = ba.z + dv * a[2]; o0.w = ba.w + dv * a[3];
    o1.x = bb.x + dv * a[4]; o1.y = bb.y + dv * a[5];
    o1.z = bb.z + dv * a[6]; o1.w = bb.w + dv * a[7];
    ((float4*)out)[node * 16 + lane * 2]     = o0;
    ((float4*)out)[node * 16 + lane * 2 + 1] = o1;
}

extern "C" void kernel_launch(void* const* d_in, const int* in_sizes, int n_in,
                              void* d_out, int out_size)
{
    const float* x  = (const float*)d_in[0];
    const int*   ei = (const int*)d_in[1];
    const float* w  = (const float*)d_in[2];
    const float* b  = (const float*)d_in[3];
    float*       out = (float*)d_out;
    (void)in_sizes; (void)n_in; (void)out_size;

    // one-time host objects (not device memory)
    static cudaStream_t s2 = nullptr;
    static cudaEvent_t evA = nullptr, evB = nullptr;
    if (!s2) {
        cudaStreamCreateWithFlags(&s2, cudaStreamNonBlocking);
        cudaEventCreateWithFlags(&evA, cudaEventDisableTiming);
        cudaEventCreateWithFlags(&evB, cudaEventDisableTiming);
    }

    k_zero <<<NBLK, 256>>>();
    k_count<<<(N_EDGES + 255) / 256, 256>>>(ei);
    k_scanF<<<NBLK, 256>>>();

    // fork: gemm depends only on dinv (scanF); runs concurrent with place
    cudaEventRecord(evA, 0);
    cudaStreamWaitEvent(s2, evA, 0);
    k_gemm<<<(N_NODES + 63) / 64, 128, 0, s2>>>(x, w);
    cudaEventRecord(evB, s2);

    k_place<<<(N_EDGES + 255) / 256, 256>>>(ei);

    // join: gather needs both place (stream 0) and gemm (s2)
    cudaStreamWaitEvent(0, evB, 0);
    long long total_threads = (long long)N_NODES * 8;
    int blocks = (int)((total_threads + 255) / 256);
    k_gather<<<blocks, 256>>>(b, out);
}